// round 4
// baseline (speedup 1.0000x reference)
#include <cuda_runtime.h>

// ---------------------------------------------------------------------------
// VQ-VAE VectorQuantizer:
//   inputs [16,256,32,32] f32, emb [8192,256] f32
//   outputs (concat, f32): loss(1) | quantized bchw (4194304) | perplexity(1)
//                          | encodings one-hot [16384,8192] (134217728)
// Numerics: replicate the JAX/XLA-CPU fp32 rounding sequence:
//   dot: sequential FMA chain over c ascending
//   d   = fl( fl(S + E2) - fl(2*dot) )
//   argmin: ascending k, strict < (first-index tie-break)
// ---------------------------------------------------------------------------

#define N_TOK   16384
#define N_CODE  8192
#define C_DIM   256
#define Q_ELEMS 4194304      // 16*256*32*32
#define ENC_OFF 4194306LL    // 1 + Q_ELEMS + 1

__device__ float  g_S[N_TOK];
__device__ float  g_E2[N_CODE];
__device__ int    g_idx[N_TOK];
__device__ int    g_counts[N_CODE];
__device__ double g_loss_part[16384];

__device__ __forceinline__ float f_inf() { return __int_as_float(0x7f800000); }

// ---------------------------------------------------------------- reset ----
__global__ void k_reset() {
    int t = blockIdx.x * blockDim.x + threadIdx.x;
    if (t < N_CODE) g_counts[t] = 0;
}

// --------------------------------------------------------- S = sum(x*x) ----
// sequential fp32: acc = fl(acc + fl(v*v)), c ascending
__global__ void k_S(const float* __restrict__ x) {
    int n = blockIdx.x * blockDim.x + threadIdx.x;
    if (n >= N_TOK) return;
    int b = n >> 10, hw = n & 1023;
    const float* p = x + (size_t)b * 262144 + hw;
    float acc = 0.0f;
    for (int c = 0; c < C_DIM; c++) {
        float v = p[(size_t)c * 1024];
        acc = __fadd_rn(acc, __fmul_rn(v, v));
    }
    g_S[n] = acc;
}

// -------------------------------------------------------- E2 = sum(e*e) ----
// (E2 ~ 1.3e-6 vs ulp(256)=3e-5: usually rounds away entirely in S+E2;
//  sequential order kept anyway for the boundary cases)
__global__ void k_E2(const float* __restrict__ emb) {
    int k = blockIdx.x * blockDim.x + threadIdx.x;
    if (k >= N_CODE) return;
    const float* p = emb + (size_t)k * C_DIM;
    float acc = 0.0f;
    for (int c = 0; c < C_DIM; c++) {
        float v = p[c];
        acc = __fadd_rn(acc, __fmul_rn(v, v));
    }
    g_E2[k] = acc;
}

// --------------------------------------------- fused GEMM + argmin tile ----
// CTA: 128 tokens x 128 codes tile, K=256 staged in 16-chunks.
// Xs [256][128] resident (128KB), Es [16][132] per chunk, e2s[128].
#define SM_XS   0
#define SM_ES   32768
#define SM_E2S  (32768 + 16 * 132)
#define SMEM_FLOATS (32768 + 16 * 132 + 128)
#define SMEM_BYTES  (SMEM_FLOATS * 4)

extern __shared__ float smem[];

__global__ void __launch_bounds__(256, 1)
k_main(const float* __restrict__ x, const float* __restrict__ emb) {
    float* Xs  = smem + SM_XS;
    float* Es  = smem + SM_ES;
    float* e2s = smem + SM_E2S;

    const int tid   = threadIdx.x;
    const int mbase = blockIdx.x * 128;
    const int b     = mbase >> 10;
    const int hw0   = mbase & 1023;
    const float* xb = x + (size_t)b * 262144 + hw0;

    // stage X tile: Xs[c*128 + m]
    for (int i = tid; i < 256 * 128; i += 256) {
        int c = i >> 7, m = i & 127;
        Xs[i] = xb[(size_t)c * 1024 + m];
    }
    __syncthreads();

    const int tm = tid >> 4;   // 0..15 row group
    const int tn = tid & 15;   // 0..15 col group

    float sreg[8];
#pragma unroll
    for (int i = 0; i < 8; i++) sreg[i] = g_S[mbase + tm * 8 + i];

    float best_v[8]; int best_i[8];
#pragma unroll
    for (int i = 0; i < 8; i++) { best_v[i] = f_inf(); best_i[i] = 0x7fffffff; }

    const int n0 = tid >> 2;   // 0..63
    const int kq = tid & 3;    // 0..3

    for (int nt = 0; nt < N_CODE / 128; nt++) {
        const int kb = nt * 128;
        __syncthreads();                       // protect e2s/Es from prev iter readers
        if (tid < 128) e2s[tid] = g_E2[kb + tid];

        float acc[8][8];
#pragma unroll
        for (int i = 0; i < 8; i++)
#pragma unroll
            for (int j = 0; j < 8; j++) acc[i][j] = 0.0f;

        for (int ko = 0; ko < C_DIM; ko += 16) {
            // stage Es[kk][n] (stride 132 to dodge bank conflicts)
#pragma unroll
            for (int p = 0; p < 2; p++) {
                int n = n0 + p * 64;
                const float4 v = *reinterpret_cast<const float4*>(
                    &emb[(size_t)(kb + n) * C_DIM + ko + kq * 4]);
                Es[(kq * 4 + 0) * 132 + n] = v.x;
                Es[(kq * 4 + 1) * 132 + n] = v.y;
                Es[(kq * 4 + 2) * 132 + n] = v.z;
                Es[(kq * 4 + 3) * 132 + n] = v.w;
            }
            __syncthreads();
#pragma unroll
            for (int kk = 0; kk < 16; kk++) {
                // FIX (R3): X tile holds all 256 c-rows; index with global
                // chunk offset ko+kk (was kk -> read c=0..15 every chunk).
                const int c = ko + kk;
                float a[8], bb[8];
                float4 a0 = *reinterpret_cast<float4*>(&Xs[c * 128 + tm * 8]);
                float4 a1 = *reinterpret_cast<float4*>(&Xs[c * 128 + tm * 8 + 4]);
                a[0]=a0.x; a[1]=a0.y; a[2]=a0.z; a[3]=a0.w;
                a[4]=a1.x; a[5]=a1.y; a[6]=a1.z; a[7]=a1.w;
                float4 b0 = *reinterpret_cast<float4*>(&Es[kk * 132 + tn * 8]);
                float4 b1 = *reinterpret_cast<float4*>(&Es[kk * 132 + tn * 8 + 4]);
                bb[0]=b0.x; bb[1]=b0.y; bb[2]=b0.z; bb[3]=b0.w;
                bb[4]=b1.x; bb[5]=b1.y; bb[6]=b1.z; bb[7]=b1.w;
#pragma unroll
                for (int i = 0; i < 8; i++)
#pragma unroll
                    for (int j = 0; j < 8; j++)
                        acc[i][j] = __fmaf_rn(a[i], bb[j], acc[i][j]);
            }
            __syncthreads();
        }

        // argmin update: d = fl(fl(S+E2) - 2*dot), k ascending within thread
#pragma unroll
        for (int j = 0; j < 8; j++) {
            int   kg = kb + tn * 8 + j;
            float e2 = e2s[tn * 8 + j];
#pragma unroll
            for (int i = 0; i < 8; i++) {
                float t = __fadd_rn(sreg[i], e2);
                float d = __fsub_rn(t, __fmul_rn(2.0f, acc[i][j]));
                if (d < best_v[i]) { best_v[i] = d; best_i[i] = kg; }
            }
        }
    }

    // cross-thread argmin reduce (16 col-groups per row), tie -> smaller idx
    __syncthreads();
    float* rv = Xs;                     // 128*16 floats
    int*   ri = (int*)(Xs + 2048);      // 128*16 ints
#pragma unroll
    for (int i = 0; i < 8; i++) {
        int row = tm * 8 + i;
        rv[row * 16 + tn] = best_v[i];
        ri[row * 16 + tn] = best_i[i];
    }
    __syncthreads();
    if (tid < 128) {
        float bv = f_inf(); int bi = 0x7fffffff;
        for (int t = 0; t < 16; t++) {
            float v  = rv[tid * 16 + t];
            int   ii = ri[tid * 16 + t];
            if (v < bv || (v == bv && ii < bi)) { bv = v; bi = ii; }
        }
        g_idx[mbase + tid] = bi;
    }
}

// --------------------------------------- quantized output + loss partial ---
__global__ void k_quant(const float* __restrict__ x, const float* __restrict__ emb,
                        float* __restrict__ outq) {
    int l = blockIdx.x * blockDim.x + threadIdx.x;
    double part = 0.0;
    if (l < Q_ELEMS) {
        int b   = l >> 18;
        int rem = l & 262143;
        int c   = rem >> 10;
        int hw  = rem & 1023;
        int n   = (b << 10) + hw;
        int idx = g_idx[n];
        float q    = __ldg(&emb[(size_t)idx * C_DIM + c]);
        float xv   = x[l];
        float diff = __fsub_rn(q, xv);               // fl(q - x)
        outq[l]    = __fadd_rn(xv, diff);            // fl(x + fl(q - x))  (ST)
        part = (double)__fmul_rn(diff, diff);        // fl(diff^2)
    }
    __shared__ double sred[256];
    sred[threadIdx.x] = part;
    __syncthreads();
    for (int s = 128; s > 0; s >>= 1) {
        if (threadIdx.x < s) sred[threadIdx.x] += sred[threadIdx.x + s];
        __syncthreads();
    }
    if (threadIdx.x == 0) g_loss_part[blockIdx.x] = sred[0];
}

// ------------------------------------------- one-hot scatter + histogram ---
__global__ void k_enc(float* __restrict__ out, long long enc_elems) {
    int n = blockIdx.x * blockDim.x + threadIdx.x;
    if (n >= N_TOK) return;
    int idx = g_idx[n];
    long long off = (long long)n * N_CODE + idx;
    if (off < enc_elems) out[ENC_OFF + off] = 1.0f;
    atomicAdd(&g_counts[idx], 1);
}

// -------------------------------------------------- loss + perplexity ------
__global__ void k_final(float* __restrict__ out, int has_full) {
    __shared__ double sred[256];
    int t = threadIdx.x;

    // H = sum_k p*log(p+1e-10), fp32 elementwise, deterministic dbl reduce
    double acc = 0.0;
    for (int k = t; k < N_CODE; k += 256) {
        float p  = (float)g_counts[k] * (1.0f / 16384.0f);   // exact
        float lg = logf(__fadd_rn(p, 1e-10f));
        acc += (double)__fmul_rn(p, lg);
    }
    sred[t] = acc; __syncthreads();
    for (int s = 128; s > 0; s >>= 1) {
        if (t < s) sred[t] += sred[t + s];
        __syncthreads();
    }
    double H = sred[0];

    // loss: deterministic sum of 16384 block partials
    double lacc = 0.0;
    for (int k = t; k < 16384; k += 256) lacc += g_loss_part[k];
    __syncthreads();
    sred[t] = lacc; __syncthreads();
    for (int s = 128; s > 0; s >>= 1) {
        if (t < s) sred[t] += sred[t + s];
        __syncthreads();
    }
    if (t == 0) {
        float m    = (float)(sred[0] / (double)Q_ELEMS);
        float loss = __fadd_rn(m, __fmul_rn(0.25f, m));      // q_loss + 0.25*e_loss
        out[0] = loss;
        if (has_full) out[1 + Q_ELEMS] = expf(-(float)H);
    }
}

// ---------------------------------------------------------------------------
extern "C" void kernel_launch(void* const* d_in, const int* in_sizes, int n_in,
                              void* d_out, int out_size) {
    const float* x   = (const float*)d_in[0];
    const float* emb = (const float*)d_in[1];
    if (n_in >= 2 && in_sizes[0] == N_CODE * C_DIM && in_sizes[1] == Q_ELEMS) {
        const float* t = x; x = emb; emb = t;   // robustness vs metadata order
    }
    float* out = (float*)d_out;

    long long enc_elems = (long long)out_size - ENC_OFF;   // expected 134217728
    int has_full = (enc_elems > 0);

    cudaFuncSetAttribute(k_main, cudaFuncAttributeMaxDynamicSharedMemorySize,
                         SMEM_BYTES);

    if (has_full)
        cudaMemsetAsync(out + ENC_OFF, 0, (size_t)enc_elems * sizeof(float), 0);

    k_reset<<<32, 256>>>();
    k_S    <<<N_TOK / 256, 256>>>(x);
    k_E2   <<<N_CODE / 256, 256>>>(emb);
    k_main <<<N_TOK / 128, 256, SMEM_BYTES>>>(x, emb);
    k_quant<<<Q_ELEMS / 256, 256>>>(x, emb, out + 1);
    k_enc  <<<N_TOK / 256, 256>>>(out, has_full ? enc_elems : 0);
    k_final<<<1, 256>>>(out, has_full);
}

// round 5
// speedup vs baseline: 1.0052x; 1.0052x over previous
#include <cuda_runtime.h>

// ---------------------------------------------------------------------------
// VQ-VAE VectorQuantizer:
//   inputs [16,256,32,32] f32, emb [8192,256] f32
//   outputs (concat, f32): loss(1) | quantized bchw (4194304) | perplexity(1)
//                          | encodings one-hot [16384,8192] (134217728)
// Numerics: replicate the JAX/XLA-CPU fp32 rounding sequence:
//   dot: sequential FMA chain over c ascending (FFMA2-packed across j outputs;
//        per-output chain order unchanged -> bitwise identical)
//   d   = fl( fl(S + E2) - fl(2*dot) )
//   argmin: ascending k, strict < (first-index tie-break)
// ---------------------------------------------------------------------------

#define N_TOK   16384
#define N_CODE  8192
#define C_DIM   256
#define Q_ELEMS 4194304      // 16*256*32*32
#define ENC_OFF 4194306LL    // 1 + Q_ELEMS + 1

__device__ float  g_S[N_TOK];
__device__ float  g_E2[N_CODE];
__device__ int    g_idx[N_TOK];
__device__ int    g_counts[N_CODE];
__device__ double g_loss_part[16384];

__device__ __forceinline__ float f_inf() { return __int_as_float(0x7f800000); }

// ---------------------------------------------------------------- reset ----
__global__ void k_reset() {
    int t = blockIdx.x * blockDim.x + threadIdx.x;
    if (t < N_CODE) g_counts[t] = 0;
}

// --------------------------------------------------------- S = sum(x*x) ----
__global__ void k_S(const float* __restrict__ x) {
    int n = blockIdx.x * blockDim.x + threadIdx.x;
    if (n >= N_TOK) return;
    int b = n >> 10, hw = n & 1023;
    const float* p = x + (size_t)b * 262144 + hw;
    float acc = 0.0f;
    for (int c = 0; c < C_DIM; c++) {
        float v = p[(size_t)c * 1024];
        acc = __fadd_rn(acc, __fmul_rn(v, v));
    }
    g_S[n] = acc;
}

// -------------------------------------------------------- E2 = sum(e*e) ----
__global__ void k_E2(const float* __restrict__ emb) {
    int k = blockIdx.x * blockDim.x + threadIdx.x;
    if (k >= N_CODE) return;
    const float* p = emb + (size_t)k * C_DIM;
    float acc = 0.0f;
    for (int c = 0; c < C_DIM; c++) {
        float v = p[c];
        acc = __fadd_rn(acc, __fmul_rn(v, v));
    }
    g_E2[k] = acc;
}

// --------------------------------------------- fused GEMM + argmin tile ----
// CTA: 128 tokens x 128 codes tile, K=256 staged in 16-chunks.
// Xs [256][128] resident (128KB), Es [16][132] per chunk, e2s[128].
// Inner product uses packed fma.rn.f32x2 (FFMA2): 2 IEEE-rn fp32 FMAs per
// instruction, pairing adjacent j-outputs. Each output's k-chain stays
// sequential -> bitwise identical to scalar FFMA version.
#define SM_XS   0
#define SM_ES   32768
#define SM_E2S  (32768 + 16 * 132)
#define SMEM_FLOATS (32768 + 16 * 132 + 128)
#define SMEM_BYTES  (SMEM_FLOATS * 4)

extern __shared__ float smem[];

__global__ void __launch_bounds__(256, 1)
k_main(const float* __restrict__ x, const float* __restrict__ emb) {
    float* Xs  = smem + SM_XS;
    float* Es  = smem + SM_ES;
    float* e2s = smem + SM_E2S;

    const int tid   = threadIdx.x;
    const int mbase = blockIdx.x * 128;
    const int b     = mbase >> 10;
    const int hw0   = mbase & 1023;
    const float* xb = x + (size_t)b * 262144 + hw0;

    // stage X tile: Xs[c*128 + m]
    for (int i = tid; i < 256 * 128; i += 256) {
        int c = i >> 7, m = i & 127;
        Xs[i] = xb[(size_t)c * 1024 + m];
    }
    __syncthreads();

    const int tm = tid >> 4;   // 0..15 row group
    const int tn = tid & 15;   // 0..15 col group

    float sreg[8];
#pragma unroll
    for (int i = 0; i < 8; i++) sreg[i] = g_S[mbase + tm * 8 + i];

    float best_v[8]; int best_i[8];
#pragma unroll
    for (int i = 0; i < 8; i++) { best_v[i] = f_inf(); best_i[i] = 0x7fffffff; }

    const int n0 = tid >> 2;   // 0..63
    const int kq = tid & 3;    // 0..3

    for (int nt = 0; nt < N_CODE / 128; nt++) {
        const int kb = nt * 128;
        __syncthreads();                       // protect e2s/Es from prev iter readers
        if (tid < 128) e2s[tid] = g_E2[kb + tid];

        // packed accumulators: acc[i][j2] holds (dot[i][2*j2], dot[i][2*j2+1])
        unsigned long long acc[8][4];
#pragma unroll
        for (int i = 0; i < 8; i++)
#pragma unroll
            for (int j = 0; j < 4; j++) acc[i][j] = 0ULL;

        for (int ko = 0; ko < C_DIM; ko += 16) {
            // stage Es[kk][n] (stride 132 to dodge bank conflicts)
#pragma unroll
            for (int p = 0; p < 2; p++) {
                int n = n0 + p * 64;
                const float4 v = *reinterpret_cast<const float4*>(
                    &emb[(size_t)(kb + n) * C_DIM + ko + kq * 4]);
                Es[(kq * 4 + 0) * 132 + n] = v.x;
                Es[(kq * 4 + 1) * 132 + n] = v.y;
                Es[(kq * 4 + 2) * 132 + n] = v.z;
                Es[(kq * 4 + 3) * 132 + n] = v.w;
            }
            __syncthreads();
#pragma unroll
            for (int kk = 0; kk < 16; kk++) {
                const int c = ko + kk;
                float4 a0 = *reinterpret_cast<float4*>(&Xs[c * 128 + tm * 8]);
                float4 a1 = *reinterpret_cast<float4*>(&Xs[c * 128 + tm * 8 + 4]);
                float a[8];
                a[0]=a0.x; a[1]=a0.y; a[2]=a0.z; a[3]=a0.w;
                a[4]=a1.x; a[5]=a1.y; a[6]=a1.z; a[7]=a1.w;
                // b pairs straight from 16B-aligned shared loads
                ulonglong2 bq0 = *reinterpret_cast<ulonglong2*>(&Es[kk * 132 + tn * 8]);
                ulonglong2 bq1 = *reinterpret_cast<ulonglong2*>(&Es[kk * 132 + tn * 8 + 4]);
                unsigned long long bp[4];
                bp[0] = bq0.x; bp[1] = bq0.y; bp[2] = bq1.x; bp[3] = bq1.y;
#pragma unroll
                for (int i = 0; i < 8; i++) {
                    unsigned long long ap;
                    unsigned int ai = __float_as_uint(a[i]);
                    asm("mov.b64 %0, {%1, %1};" : "=l"(ap) : "r"(ai));
#pragma unroll
                    for (int j = 0; j < 4; j++)
                        asm("fma.rn.f32x2 %0, %1, %2, %0;"
                            : "+l"(acc[i][j]) : "l"(ap), "l"(bp[j]));
                }
            }
            __syncthreads();
        }

        // argmin update: d = fl(fl(S+E2) - 2*dot), k ascending within thread
#pragma unroll
        for (int j2 = 0; j2 < 4; j2++) {
#pragma unroll
            for (int h = 0; h < 2; h++) {              // low half = even j
                int   j  = j2 * 2 + h;
                int   kg = kb + tn * 8 + j;
                float e2 = e2s[tn * 8 + j];
#pragma unroll
                for (int i = 0; i < 8; i++) {
                    float2 dp = *reinterpret_cast<float2*>(&acc[i][j2]);
                    float dot = h ? dp.y : dp.x;
                    float t = __fadd_rn(sreg[i], e2);
                    float d = __fsub_rn(t, __fmul_rn(2.0f, dot));
                    if (d < best_v[i]) { best_v[i] = d; best_i[i] = kg; }
                }
            }
        }
    }

    // cross-thread argmin reduce (16 col-groups per row), tie -> smaller idx
    __syncthreads();
    float* rv = Xs;                     // 128*16 floats
    int*   ri = (int*)(Xs + 2048);      // 128*16 ints
#pragma unroll
    for (int i = 0; i < 8; i++) {
        int row = tm * 8 + i;
        rv[row * 16 + tn] = best_v[i];
        ri[row * 16 + tn] = best_i[i];
    }
    __syncthreads();
    if (tid < 128) {
        float bv = f_inf(); int bi = 0x7fffffff;
        for (int t = 0; t < 16; t++) {
            float v  = rv[tid * 16 + t];
            int   ii = ri[tid * 16 + t];
            if (v < bv || (v == bv && ii < bi)) { bv = v; bi = ii; }
        }
        g_idx[mbase + tid] = bi;
    }
}

// --------------------------------------- quantized output + loss partial ---
__global__ void k_quant(const float* __restrict__ x, const float* __restrict__ emb,
                        float* __restrict__ outq) {
    int l = blockIdx.x * blockDim.x + threadIdx.x;
    double part = 0.0;
    if (l < Q_ELEMS) {
        int b   = l >> 18;
        int rem = l & 262143;
        int c   = rem >> 10;
        int hw  = rem & 1023;
        int n   = (b << 10) + hw;
        int idx = g_idx[n];
        float q    = __ldg(&emb[(size_t)idx * C_DIM + c]);
        float xv   = x[l];
        float diff = __fsub_rn(q, xv);               // fl(q - x)
        outq[l]    = __fadd_rn(xv, diff);            // fl(x + fl(q - x))  (ST)
        part = (double)__fmul_rn(diff, diff);        // fl(diff^2)
    }
    __shared__ double sred[256];
    sred[threadIdx.x] = part;
    __syncthreads();
    for (int s = 128; s > 0; s >>= 1) {
        if (threadIdx.x < s) sred[threadIdx.x] += sred[threadIdx.x + s];
        __syncthreads();
    }
    if (threadIdx.x == 0) g_loss_part[blockIdx.x] = sred[0];
}

// ------------------------------------------- one-hot scatter + histogram ---
__global__ void k_enc(float* __restrict__ out, long long enc_elems) {
    int n = blockIdx.x * blockDim.x + threadIdx.x;
    if (n >= N_TOK) return;
    int idx = g_idx[n];
    long long off = (long long)n * N_CODE + idx;
    if (off < enc_elems) out[ENC_OFF + off] = 1.0f;
    atomicAdd(&g_counts[idx], 1);
}

// -------------------------------------------------- loss + perplexity ------
__global__ void k_final(float* __restrict__ out, int has_full) {
    __shared__ double sred[256];
    int t = threadIdx.x;

    // H = sum_k p*log(p+1e-10), fp32 elementwise, deterministic dbl reduce
    double acc = 0.0;
    for (int k = t; k < N_CODE; k += 256) {
        float p  = (float)g_counts[k] * (1.0f / 16384.0f);   // exact
        float lg = logf(__fadd_rn(p, 1e-10f));
        acc += (double)__fmul_rn(p, lg);
    }
    sred[t] = acc; __syncthreads();
    for (int s = 128; s > 0; s >>= 1) {
        if (t < s) sred[t] += sred[t + s];
        __syncthreads();
    }
    double H = sred[0];

    // loss: deterministic sum of 16384 block partials
    double lacc = 0.0;
    for (int k = t; k < 16384; k += 256) lacc += g_loss_part[k];
    __syncthreads();
    sred[t] = lacc; __syncthreads();
    for (int s = 128; s > 0; s >>= 1) {
        if (t < s) sred[t] += sred[t + s];
        __syncthreads();
    }
    if (t == 0) {
        float m    = (float)(sred[0] / (double)Q_ELEMS);
        float loss = __fadd_rn(m, __fmul_rn(0.25f, m));      // q_loss + 0.25*e_loss
        out[0] = loss;
        if (has_full) out[1 + Q_ELEMS] = expf(-(float)H);
    }
}

// ---------------------------------------------------------------------------
extern "C" void kernel_launch(void* const* d_in, const int* in_sizes, int n_in,
                              void* d_out, int out_size) {
    const float* x   = (const float*)d_in[0];
    const float* emb = (const float*)d_in[1];
    if (n_in >= 2 && in_sizes[0] == N_CODE * C_DIM && in_sizes[1] == Q_ELEMS) {
        const float* t = x; x = emb; emb = t;   // robustness vs metadata order
    }
    float* out = (float*)d_out;

    long long enc_elems = (long long)out_size - ENC_OFF;   // expected 134217728
    int has_full = (enc_elems > 0);

    cudaFuncSetAttribute(k_main, cudaFuncAttributeMaxDynamicSharedMemorySize,
                         SMEM_BYTES);

    if (has_full)
        cudaMemsetAsync(out + ENC_OFF, 0, (size_t)enc_elems * sizeof(float), 0);

    k_reset<<<32, 256>>>();
    k_S    <<<N_TOK / 256, 256>>>(x);
    k_E2   <<<N_CODE / 256, 256>>>(emb);
    k_main <<<N_TOK / 128, 256, SMEM_BYTES>>>(x, emb);
    k_quant<<<Q_ELEMS / 256, 256>>>(x, emb, out + 1);
    k_enc  <<<N_TOK / 256, 256>>>(out, has_full ? enc_elems : 0);
    k_final<<<1, 256>>>(out, has_full);
}

// round 7
// speedup vs baseline: 1.4134x; 1.4061x over previous
#include <cuda_runtime.h>
#include <cuda_bf16.h>
#include <cstdint>

// ---------------------------------------------------------------------------
// VQ-VAE VectorQuantizer on GB300 (sm_103, no 'a' features available in PTX).
// Strategy: warp-level bf16 mma.sync computes approximate distances; rigorous
// error window collects a tiny candidate set per token; exact sequential
// fp32-FMA recompute (bit-identical to XLA, proven rel_err=0.0 in R4) picks
// the final argmin with first-index tie-break.
// ---------------------------------------------------------------------------

#define N_TOK   16384
#define N_CODE  8192
#define C_DIM   256
#define Q_ELEMS 4194304      // 16*256*32*32
#define ENC_OFF 4194306LL    // 1 + Q_ELEMS + 1
#define CAP     96

__device__ float    g_S[N_TOK];
__device__ float    g_L1[N_TOK];
__device__ float    g_E2[N_CODE];
__device__ int      g_idx[N_TOK];
__device__ int      g_counts[N_CODE];
__device__ double   g_loss_part[16384];
__device__ int      g_cand[N_TOK][CAP];
__device__ int      g_cnt[N_TOK];
__device__ unsigned g_maxe_bits;

__device__ __forceinline__ float f_inf() { return __int_as_float(0x7f800000); }

__device__ __forceinline__ uint32_t smem_u32(const void* p) {
    uint32_t a;
    asm("{ .reg .u64 t; cvta.to.shared.u64 t, %1; cvt.u32.u64 %0, t; }"
        : "=r"(a) : "l"(p));
    return a;
}
#define LDSM_X4(r0, r1, r2, r3, addr)                                          \
    asm volatile("ldmatrix.sync.aligned.m8n8.x4.shared.b16 {%0,%1,%2,%3}, [%4];" \
        : "=r"(r0), "=r"(r1), "=r"(r2), "=r"(r3) : "r"(addr))
#define MMA_BF16(c0, c1, c2, c3, a0, a1, a2, a3, b0, b1)                       \
    asm volatile("mma.sync.aligned.m16n8k16.row.col.f32.bf16.bf16.f32 "       \
        "{%0,%1,%2,%3},{%4,%5,%6,%7},{%8,%9},{%0,%1,%2,%3};"                  \
        : "+f"(c0), "+f"(c1), "+f"(c2), "+f"(c3)                               \
        : "r"(a0), "r"(a1), "r"(a2), "r"(a3), "r"(b0), "r"(b1))

// ---------------------------------------------------------------- reset ----
__global__ void k_reset() {
    int t = blockIdx.x * blockDim.x + threadIdx.x;
    if (t < N_CODE) g_counts[t] = 0;
    if (t < N_TOK)  g_cnt[t] = 0;
    if (t == 0)     g_maxe_bits = 0;
}

// ----------------------------------------------- S = sum(x*x), L1 = sum|x| --
__global__ void k_S(const float* __restrict__ x) {
    int n = blockIdx.x * blockDim.x + threadIdx.x;
    if (n >= N_TOK) return;
    int b = n >> 10, hw = n & 1023;
    const float* p = x + (size_t)b * 262144 + hw;
    float acc = 0.0f, l1 = 0.0f;
    for (int c = 0; c < C_DIM; c++) {
        float v = p[(size_t)c * 1024];
        acc = __fadd_rn(acc, __fmul_rn(v, v));
        l1 += fabsf(v);
    }
    g_S[n] = acc;
    g_L1[n] = l1;
}

// ----------------------------------------- E2 = sum(e*e), track max |e| ----
__global__ void k_E2(const float* __restrict__ emb) {
    int k = blockIdx.x * blockDim.x + threadIdx.x;
    if (k >= N_CODE) return;
    const float* p = emb + (size_t)k * C_DIM;
    float acc = 0.0f, mx = 0.0f;
    for (int c = 0; c < C_DIM; c++) {
        float v = p[c];
        acc = __fadd_rn(acc, __fmul_rn(v, v));
        mx = fmaxf(mx, fabsf(v));
    }
    g_E2[k] = acc;
    atomicMax(&g_maxe_bits, __float_as_uint(mx));   // positive: uint order == float order
}

// ----------------------- bf16 mma.sync approx distances + candidate filter --
// CTA = 128 tokens x all 8192 codes (64 n-tiles of 128). A resident in smem
// (bf16, padded 528B rows), E double-buffered. 8 warps, warp tile 16 tokens x
// 128 codes per n-tile. Filter: keep k if d_ap(k) < runmin + W where
// W = 2*max-distance-error (superset of exact argmin, proof in notes).
#define RS      528              // padded row stride bytes (264 halves)
#define SM_E2S  0                // 2 x 128 f32
#define SM_A    1024             // 128 rows * 528B = 67584
#define SM_EB0  68608
#define SM_EB1  136192
#define SMEM_DYN 203776

__global__ void __launch_bounds__(256, 1)
k_mma(const float* __restrict__ x, const float* __restrict__ emb) {
    extern __shared__ char sm[];
    float* e2s = (float*)(sm + SM_E2S);
    const uint32_t sb = smem_u32(sm);
    const uint32_t sA = sb + SM_A;

    const int tid = threadIdx.x, w = tid >> 5, lane = tid & 31;
    const int mbase = blockIdx.x * 128;
    const int b     = mbase >> 10;
    const int hw0   = mbase & 1023;
    const float* xb = x + (size_t)b * 262144 + hw0;

    // ---- stage A: 128 tokens x 256 c, bf16, padded rows ----
    for (int i = tid; i < 128 * 32; i += 256) {
        int m = i & 127, c0 = (i >> 7) * 8;
        float v0 = xb[(size_t)(c0 + 0) * 1024 + m];
        float v1 = xb[(size_t)(c0 + 1) * 1024 + m];
        float v2 = xb[(size_t)(c0 + 2) * 1024 + m];
        float v3 = xb[(size_t)(c0 + 3) * 1024 + m];
        float v4 = xb[(size_t)(c0 + 4) * 1024 + m];
        float v5 = xb[(size_t)(c0 + 5) * 1024 + m];
        float v6 = xb[(size_t)(c0 + 6) * 1024 + m];
        float v7 = xb[(size_t)(c0 + 7) * 1024 + m];
        __nv_bfloat162 h0 = __floats2bfloat162_rn(v0, v1);
        __nv_bfloat162 h1 = __floats2bfloat162_rn(v2, v3);
        __nv_bfloat162 h2 = __floats2bfloat162_rn(v4, v5);
        __nv_bfloat162 h3 = __floats2bfloat162_rn(v6, v7);
        uint4 pk;
        pk.x = *(uint32_t*)&h0; pk.y = *(uint32_t*)&h1;
        pk.z = *(uint32_t*)&h2; pk.w = *(uint32_t*)&h3;
        *(uint4*)(sm + SM_A + m * RS + c0 * 2) = pk;
    }

    // ---- E tile staging helper (n-tile nt -> buffer buf) ----
    auto stage_E = [&](int nt, int buf) {
        const int kb = nt * 128;
        char* eb = sm + (buf ? SM_EB1 : SM_EB0);
        for (int i = tid; i < 4096; i += 256) {          // 128 rows x 32 c-segs
            int row = i >> 5, c0 = (i & 31) * 8;
            const float4 v0 = *(const float4*)&emb[(size_t)(kb + row) * 256 + c0];
            const float4 v1 = *(const float4*)&emb[(size_t)(kb + row) * 256 + c0 + 4];
            __nv_bfloat162 h0 = __floats2bfloat162_rn(v0.x, v0.y);
            __nv_bfloat162 h1 = __floats2bfloat162_rn(v0.z, v0.w);
            __nv_bfloat162 h2 = __floats2bfloat162_rn(v1.x, v1.y);
            __nv_bfloat162 h3 = __floats2bfloat162_rn(v1.z, v1.w);
            uint4 pk;
            pk.x = *(uint32_t*)&h0; pk.y = *(uint32_t*)&h1;
            pk.z = *(uint32_t*)&h2; pk.w = *(uint32_t*)&h3;
            *(uint4*)(eb + row * RS + c0 * 2) = pk;
        }
        for (int i = tid; i < 128; i += 256) e2s[buf * 128 + i] = g_E2[kb + i];
    };

    stage_E(0, 0);
    __syncthreads();

    // ---- hoist A fragments: 16 k-steps x 4 regs ----
    uint32_t a[16][4];
    {
        uint32_t abase = sA + (uint32_t)(w * 16 + (lane & 15)) * RS + ((lane >> 4) & 1) * 16;
#pragma unroll
        for (int k = 0; k < 16; k++)
            LDSM_X4(a[k][0], a[k][1], a[k][2], a[k][3], abase + k * 32);
    }

    // ---- per-token filter state (2 token rows per lane) ----
    const int   tok0 = mbase + w * 16 + (lane >> 2);
    const int   tok1 = tok0 + 8;
    const float S0 = g_S[tok0], S1 = g_S[tok1];
    const float maxe = __uint_as_float(g_maxe_bits);
    const float W0 = __fmaf_rn(0.0313f * maxe, g_L1[tok0], 1.3e-4f);
    const float W1 = __fmaf_rn(0.0313f * maxe, g_L1[tok1], 1.3e-4f);
    float rm0 = f_inf(), rm1 = f_inf(), thr0 = f_inf(), thr1 = f_inf();

    for (int nt = 0; nt < 64; nt++) {
        if (nt + 1 < 64) stage_E(nt + 1, (nt + 1) & 1);

        const uint32_t eB = sb + ((nt & 1) ? SM_EB1 : SM_EB0);
        const float*   e2 = e2s + (nt & 1) * 128;
        const int      kb = nt * 128;
        const uint32_t bbase = eB + (uint32_t)(lane & 15) * RS + ((lane >> 4) & 1) * 16;

#pragma unroll 1
        for (int fp = 0; fp < 8; fp++) {
            float c00 = 0.f, c01 = 0.f, c02 = 0.f, c03 = 0.f;
            float c10 = 0.f, c11 = 0.f, c12 = 0.f, c13 = 0.f;
            const uint32_t baddr = bbase + (uint32_t)fp * 16 * RS;
#pragma unroll
            for (int k = 0; k < 16; k++) {
                uint32_t b0, b1, b2, b3;
                LDSM_X4(b0, b1, b2, b3, baddr + k * 32);
                MMA_BF16(c00, c01, c02, c03, a[k][0], a[k][1], a[k][2], a[k][3], b0, b2);
                MMA_BF16(c10, c11, c12, c13, a[k][0], a[k][1], a[k][2], a[k][3], b1, b3);
            }
            // epilogue: d = (S + E2) - 2*dot ; capture candidates
#pragma unroll
            for (int h = 0; h < 2; h++) {
                const int   f   = fp * 2 + h;
                const int   cA  = f * 8 + (lane & 3) * 2;
                const float e2a = e2[cA], e2b = e2[cA + 1];
                const int   colA = kb + cA, colB = colA + 1;
                float dA0 = __fsub_rn(__fadd_rn(S0, e2a), __fmul_rn(2.0f, h ? c10 : c00));
                float dB0 = __fsub_rn(__fadd_rn(S0, e2b), __fmul_rn(2.0f, h ? c11 : c01));
                float dA1 = __fsub_rn(__fadd_rn(S1, e2a), __fmul_rn(2.0f, h ? c12 : c02));
                float dB1 = __fsub_rn(__fadd_rn(S1, e2b), __fmul_rn(2.0f, h ? c13 : c03));
                if (dA0 < thr0) {
                    int s = atomicAdd(&g_cnt[tok0], 1);
                    if (s < CAP) g_cand[tok0][s] = colA;
                    if (dA0 < rm0) { rm0 = dA0; thr0 = __fadd_rn(dA0, W0); }
                }
                if (dB0 < thr0) {
                    int s = atomicAdd(&g_cnt[tok0], 1);
                    if (s < CAP) g_cand[tok0][s] = colB;
                    if (dB0 < rm0) { rm0 = dB0; thr0 = __fadd_rn(dB0, W0); }
                }
                if (dA1 < thr1) {
                    int s = atomicAdd(&g_cnt[tok1], 1);
                    if (s < CAP) g_cand[tok1][s] = colA;
                    if (dA1 < rm1) { rm1 = dA1; thr1 = __fadd_rn(dA1, W1); }
                }
                if (dB1 < thr1) {
                    int s = atomicAdd(&g_cnt[tok1], 1);
                    if (s < CAP) g_cand[tok1][s] = colB;
                    if (dB1 < rm1) { rm1 = dB1; thr1 = __fadd_rn(dB1, W1); }
                }
            }
        }
        // tighten thresholds across the 4 lanes sharing the same token rows
#pragma unroll
        for (int off = 1; off < 4; off <<= 1) {
            rm0 = fminf(rm0, __shfl_xor_sync(0xffffffff, rm0, off));
            rm1 = fminf(rm1, __shfl_xor_sync(0xffffffff, rm1, off));
        }
        thr0 = __fadd_rn(rm0, W0);
        thr1 = __fadd_rn(rm1, W1);
        __syncthreads();
    }
}

// ------------------------------------- exact refinement (bit-exact argmin) --
__global__ void k_refine(const float* __restrict__ x, const float* __restrict__ emb) {
    __shared__ float xs[8][256];
    const int w = threadIdx.x >> 5, lane = threadIdx.x & 31;
    const int n = blockIdx.x * 8 + w;
    const int b = n >> 10, hw = n & 1023;
    const float* xb = x + (size_t)b * 262144 + hw;
    for (int c = lane; c < 256; c += 32) xs[w][c] = xb[(size_t)c * 1024];
    __syncwarp();

    const float S = g_S[n];
    const int cnt = g_cnt[n];
    float bd = f_inf(); int bi = 0x7fffffff;

    auto exact_d = [&](int k) -> float {
        const float* e = emb + (size_t)k * 256;
        float acc = 0.0f;
#pragma unroll 8
        for (int c = 0; c < 256; c++)
            acc = __fmaf_rn(xs[w][c], e[c], acc);       // sequential chain, c asc
        float t = __fadd_rn(S, g_E2[k]);
        return __fsub_rn(t, __fmul_rn(2.0f, acc));
    };

    if (cnt > CAP) {                                    // overflow: full scan
        for (int k = lane; k < N_CODE; k += 32) {
            float d = exact_d(k);
            if (d < bd || (d == bd && k < bi)) { bd = d; bi = k; }
        }
    } else {
        for (int ci = lane; ci < cnt; ci += 32) {
            int k = g_cand[n][ci];
            float d = exact_d(k);
            if (d < bd || (d == bd && k < bi)) { bd = d; bi = k; }
        }
    }
#pragma unroll
    for (int off = 16; off > 0; off >>= 1) {
        float od = __shfl_down_sync(0xffffffff, bd, off);
        int   oi = __shfl_down_sync(0xffffffff, bi, off);
        if (od < bd || (od == bd && oi < bi)) { bd = od; bi = oi; }
    }
    if (lane == 0) g_idx[n] = bi;
}

// --------------------------------- quantized output + loss partial ----------
__global__ void k_quant(const float* __restrict__ x, const float* __restrict__ emb,
                        float* __restrict__ outq) {
    int l = blockIdx.x * blockDim.x + threadIdx.x;
    double part = 0.0;
    if (l < Q_ELEMS) {
        int b   = l >> 18;
        int rem = l & 262143;
        int c   = rem >> 10;
        int hw  = rem & 1023;
        int n   = (b << 10) + hw;
        int idx = g_idx[n];
        float q    = __ldg(&emb[(size_t)idx * C_DIM + c]);
        float xv   = x[l];
        float diff = __fsub_rn(q, xv);
        outq[l]    = __fadd_rn(xv, diff);               // straight-through
        part = (double)__fmul_rn(diff, diff);
    }
    __shared__ double sred[256];
    sred[threadIdx.x] = part;
    __syncthreads();
    for (int s = 128; s > 0; s >>= 1) {
        if (threadIdx.x < s) sred[threadIdx.x] += sred[threadIdx.x + s];
        __syncthreads();
    }
    if (threadIdx.x == 0) g_loss_part[blockIdx.x] = sred[0];
}

// ------------------------------------------- one-hot scatter + histogram ----
__global__ void k_enc(float* __restrict__ out, long long enc_elems) {
    int n = blockIdx.x * blockDim.x + threadIdx.x;
    if (n >= N_TOK) return;
    int idx = g_idx[n];
    long long off = (long long)n * N_CODE + idx;
    if (off < enc_elems) out[ENC_OFF + off] = 1.0f;
    atomicAdd(&g_counts[idx], 1);
}

// -------------------------------------------------- loss + perplexity -------
__global__ void k_final(float* __restrict__ out, int has_full) {
    __shared__ double sred[256];
    int t = threadIdx.x;
    double acc = 0.0;
    for (int k = t; k < N_CODE; k += 256) {
        float p  = (float)g_counts[k] * (1.0f / 16384.0f);
        float lg = logf(__fadd_rn(p, 1e-10f));
        acc += (double)__fmul_rn(p, lg);
    }
    sred[t] = acc; __syncthreads();
    for (int s = 128; s > 0; s >>= 1) {
        if (t < s) sred[t] += sred[t + s];
        __syncthreads();
    }
    double H = sred[0];

    double lacc = 0.0;
    for (int k = t; k < 16384; k += 256) lacc += g_loss_part[k];
    __syncthreads();
    sred[t] = lacc; __syncthreads();
    for (int s = 128; s > 0; s >>= 1) {
        if (t < s) sred[t] += sred[t + s];
        __syncthreads();
    }
    if (t == 0) {
        float m    = (float)(sred[0] / (double)Q_ELEMS);
        float loss = __fadd_rn(m, __fmul_rn(0.25f, m));
        out[0] = loss;
        if (has_full) out[1 + Q_ELEMS] = expf(-(float)H);
    }
}

// ---------------------------------------------------------------------------
extern "C" void kernel_launch(void* const* d_in, const int* in_sizes, int n_in,
                              void* d_out, int out_size) {
    const float* x   = (const float*)d_in[0];
    const float* emb = (const float*)d_in[1];
    if (n_in >= 2 && in_sizes[0] == N_CODE * C_DIM && in_sizes[1] == Q_ELEMS) {
        const float* t = x; x = emb; emb = t;
    }
    float* out = (float*)d_out;

    long long enc_elems = (long long)out_size - ENC_OFF;
    int has_full = (enc_elems > 0);

    cudaFuncSetAttribute(k_mma, cudaFuncAttributeMaxDynamicSharedMemorySize,
                         SMEM_DYN);

    if (has_full)
        cudaMemsetAsync(out + ENC_OFF, 0, (size_t)enc_elems * sizeof(float), 0);

    k_reset <<<64, 256>>>();
    k_S     <<<N_TOK / 256, 256>>>(x);
    k_E2    <<<N_CODE / 256, 256>>>(emb);
    k_mma   <<<N_TOK / 128, 256, SMEM_DYN>>>(x, emb);
    k_refine<<<N_TOK / 8, 256>>>(x, emb);
    k_quant <<<Q_ELEMS / 256, 256>>>(x, emb, out + 1);
    k_enc   <<<N_TOK / 256, 256>>>(out, has_full ? enc_elems : 0);
    k_final <<<1, 256>>>(out, has_full);
}